// round 2
// baseline (speedup 1.0000x reference)
#include <cuda_runtime.h>
#include <math.h>

#define B_  2
#define S_  2048
#define D_  1024
#define H_  16
#define HD_ 64
#define M_  (B_*S_)   // 4096 rows

// Scratch (allocation-free rule: __device__ globals)
__device__ float g_Q[B_*H_*S_*HD_];
__device__ float g_K[B_*H_*S_*HD_];
__device__ float g_V[B_*H_*S_*HD_];
__device__ float g_A[B_*S_*D_];     // attention output, [B,S,D]

// ---------------------------------------------------------------------------
// Fused QKV projection: y = x @ W^T for Wq,Wk,Wv.
// 64x64 output tile per block, 256 threads, 4x4 per thread, K-step 16.
// Q is pre-scaled by 1/sqrt(HD)=0.125 and all three stored in [B,H,S,HD].
// ---------------------------------------------------------------------------
__global__ __launch_bounds__(256) void qkv_proj(const float* __restrict__ x,
                                                const float* __restrict__ Wq,
                                                const float* __restrict__ Wk,
                                                const float* __restrict__ Wv)
{
    __shared__ float Xs[64][17];
    __shared__ float Ws_[3][64][17];

    const int tid = threadIdx.x;
    const int tx  = tid & 15;
    const int ty  = tid >> 4;
    const int row0 = blockIdx.x * 64;   // over B*S
    const int col0 = blockIdx.y * 64;   // over D

    // vectorized tile-fill indices: 64 rows x 16 cols = 256 float4
    const int fr = tid >> 2;        // row 0..63
    const int fc = (tid & 3) * 4;   // col 0,4,8,12

    float acc[3][4][4];
#pragma unroll
    for (int m = 0; m < 3; m++)
#pragma unroll
        for (int u = 0; u < 4; u++)
#pragma unroll
            for (int v = 0; v < 4; v++) acc[m][u][v] = 0.f;

    for (int k0 = 0; k0 < D_; k0 += 16) {
        {
            float4 xv = *(const float4*)&x [(size_t)(row0 + fr) * D_ + k0 + fc];
            float4 qv = *(const float4*)&Wq[(size_t)(col0 + fr) * D_ + k0 + fc];
            float4 kv = *(const float4*)&Wk[(size_t)(col0 + fr) * D_ + k0 + fc];
            float4 vv = *(const float4*)&Wv[(size_t)(col0 + fr) * D_ + k0 + fc];
            Xs[fr][fc+0] = xv.x; Xs[fr][fc+1] = xv.y; Xs[fr][fc+2] = xv.z; Xs[fr][fc+3] = xv.w;
            Ws_[0][fr][fc+0] = qv.x; Ws_[0][fr][fc+1] = qv.y; Ws_[0][fr][fc+2] = qv.z; Ws_[0][fr][fc+3] = qv.w;
            Ws_[1][fr][fc+0] = kv.x; Ws_[1][fr][fc+1] = kv.y; Ws_[1][fr][fc+2] = kv.z; Ws_[1][fr][fc+3] = kv.w;
            Ws_[2][fr][fc+0] = vv.x; Ws_[2][fr][fc+1] = vv.y; Ws_[2][fr][fc+2] = vv.z; Ws_[2][fr][fc+3] = vv.w;
        }
        __syncthreads();
#pragma unroll
        for (int kk = 0; kk < 16; kk++) {
            float a4[4];
#pragma unroll
            for (int u = 0; u < 4; u++) a4[u] = Xs[ty*4 + u][kk];
            float w4[3][4];
#pragma unroll
            for (int m = 0; m < 3; m++)
#pragma unroll
                for (int v = 0; v < 4; v++) w4[m][v] = Ws_[m][tx*4 + v][kk];
#pragma unroll
            for (int m = 0; m < 3; m++)
#pragma unroll
                for (int u = 0; u < 4; u++)
#pragma unroll
                    for (int v = 0; v < 4; v++)
                        acc[m][u][v] += a4[u] * w4[m][v];
        }
        __syncthreads();
    }

#pragma unroll
    for (int u = 0; u < 4; u++) {
        int i = row0 + ty*4 + u;
        int b = i / S_, s = i % S_;
#pragma unroll
        for (int v = 0; v < 4; v++) {
            int j  = col0 + tx*4 + v;
            int h  = j >> 6, hd = j & 63;
            int idx = ((b*H_ + h)*S_ + s)*HD_ + hd;
            g_Q[idx] = acc[0][u][v] * 0.125f;   // 1/sqrt(64)
            g_K[idx] = acc[1][u][v];
            g_V[idx] = acc[2][u][v];
        }
    }
}

// ---------------------------------------------------------------------------
// Flash attention with ALiBi + causal. One CTA per (b, h, 64-query tile).
// Online softmax, 64x64 key tiles, upper-triangle tiles skipped.
// Dynamic smem: Qs, Ks, Vs, Ps each [64][68] floats = 69,632 B.
// ---------------------------------------------------------------------------
#define FLASH_SMEM (4 * 64 * 68 * sizeof(float))

__global__ __launch_bounds__(256) void flash_attn()
{
    extern __shared__ float sm[];
    float (*Qs)[68] = (float (*)[68])(sm);
    float (*Ks)[68] = (float (*)[68])(sm + 1*64*68);
    float (*Vs)[68] = (float (*)[68])(sm + 2*64*68);
    float (*Ps)[68] = (float (*)[68])(sm + 3*64*68);

    const int t = blockIdx.x;     // query tile
    const int h = blockIdx.y;
    const int b = blockIdx.z;
    const int tid = threadIdx.x;
    const int tx = tid & 15, ty = tid >> 4;

    const float* Qp = g_Q + ((size_t)(b*H_ + h)*S_ + t*64) * HD_;
    const float* Kp = g_K + ((size_t)(b*H_ + h)*S_) * HD_;
    const float* Vp = g_V + ((size_t)(b*H_ + h)*S_) * HD_;

    // vectorized stage: 64 rows x 64 cols = 1024 float4, 256 threads -> 4 iters
#pragma unroll
    for (int it = 0; it < 4; it++) {
        int l = it * 256 + tid;          // float4 index
        int r = l >> 4, c = (l & 15) * 4;
        float4 qv = *(const float4*)&Qp[r*HD_ + c];
        Qs[r][c+0] = qv.x; Qs[r][c+1] = qv.y; Qs[r][c+2] = qv.z; Qs[r][c+3] = qv.w;
    }

    float o[4][4];
    float mrow[4], lrow[4];
#pragma unroll
    for (int u = 0; u < 4; u++) {
        mrow[u] = -INFINITY; lrow[u] = 0.f;
#pragma unroll
        for (int v = 0; v < 4; v++) o[u][v] = 0.f;
    }
    const float slope = exp2f(-0.5f * (float)(h + 1));
    int qrow[4];
#pragma unroll
    for (int u = 0; u < 4; u++) qrow[u] = t*64 + ty*4 + u;

    __syncthreads();

    for (int j0 = 0; j0 <= t*64; j0 += 64) {
#pragma unroll
        for (int it = 0; it < 4; it++) {
            int l = it * 256 + tid;
            int r = l >> 4, c = (l & 15) * 4;
            float4 kv = *(const float4*)&Kp[(size_t)(j0 + r)*HD_ + c];
            float4 vv = *(const float4*)&Vp[(size_t)(j0 + r)*HD_ + c];
            Ks[r][c+0] = kv.x; Ks[r][c+1] = kv.y; Ks[r][c+2] = kv.z; Ks[r][c+3] = kv.w;
            Vs[r][c+0] = vv.x; Vs[r][c+1] = vv.y; Vs[r][c+2] = vv.z; Vs[r][c+3] = vv.w;
        }
        __syncthreads();

        // S = Q @ K^T (Q already scaled)
        float s[4][4];
#pragma unroll
        for (int u = 0; u < 4; u++)
#pragma unroll
            for (int v = 0; v < 4; v++) s[u][v] = 0.f;
#pragma unroll 8
        for (int kk = 0; kk < 64; kk++) {
            float qf[4], kf[4];
#pragma unroll
            for (int u = 0; u < 4; u++) qf[u] = Qs[ty*4 + u][kk];
#pragma unroll
            for (int v = 0; v < 4; v++) kf[v] = Ks[tx*4 + v][kk];
#pragma unroll
            for (int u = 0; u < 4; u++)
#pragma unroll
                for (int v = 0; v < 4; v++) s[u][v] += qf[u] * kf[v];
        }

        // ALiBi bias + causal mask (diagonal tile only)
        const bool diag = (j0 == t*64);
#pragma unroll
        for (int u = 0; u < 4; u++)
#pragma unroll
            for (int v = 0; v < 4; v++) {
                int j = j0 + tx*4 + v;
                s[u][v] += slope * (float)(j - qrow[u]);
                if (diag && j > qrow[u]) s[u][v] = -1e30f;
            }

        // online softmax update
#pragma unroll
        for (int u = 0; u < 4; u++) {
            float mx = fmaxf(fmaxf(s[u][0], s[u][1]), fmaxf(s[u][2], s[u][3]));
#pragma unroll
            for (int d = 1; d < 16; d <<= 1)
                mx = fmaxf(mx, __shfl_xor_sync(0xffffffffu, mx, d));
            float mnew  = fmaxf(mrow[u], mx);
            float alpha = __expf(mrow[u] - mnew);
            float ls = 0.f;
#pragma unroll
            for (int v = 0; v < 4; v++) {
                s[u][v] = __expf(s[u][v] - mnew);
                ls += s[u][v];
            }
#pragma unroll
            for (int d = 1; d < 16; d <<= 1)
                ls += __shfl_xor_sync(0xffffffffu, ls, d);
            lrow[u] = lrow[u] * alpha + ls;
            mrow[u] = mnew;
#pragma unroll
            for (int v = 0; v < 4; v++) o[u][v] *= alpha;
        }

        // P -> smem, then O += P @ V
#pragma unroll
        for (int u = 0; u < 4; u++)
#pragma unroll
            for (int v = 0; v < 4; v++) Ps[ty*4 + u][tx*4 + v] = s[u][v];
        __syncthreads();

#pragma unroll 8
        for (int kk = 0; kk < 64; kk++) {
            float pf[4], vf[4];
#pragma unroll
            for (int u = 0; u < 4; u++) pf[u] = Ps[ty*4 + u][kk];
#pragma unroll
            for (int v = 0; v < 4; v++) vf[v] = Vs[kk][tx*4 + v];
#pragma unroll
            for (int u = 0; u < 4; u++)
#pragma unroll
                for (int v = 0; v < 4; v++) o[u][v] += pf[u] * vf[v];
        }
        __syncthreads();
    }

    // normalize + write to [B,S,D]
#pragma unroll
    for (int u = 0; u < 4; u++) {
        float inv = 1.0f / lrow[u];
        int i = t*64 + ty*4 + u;
#pragma unroll
        for (int v = 0; v < 4; v++) {
            int c = h*64 + tx*4 + v;
            g_A[((size_t)b*S_ + i)*D_ + c] = o[u][v] * inv;
        }
    }
}

// ---------------------------------------------------------------------------
// Output projection: out = A @ Wo^T
// ---------------------------------------------------------------------------
__global__ __launch_bounds__(256) void out_proj(const float* __restrict__ Wo,
                                                float* __restrict__ out)
{
    __shared__ float As[64][17];
    __shared__ float Ws[64][17];

    const int tid = threadIdx.x;
    const int tx  = tid & 15;
    const int ty  = tid >> 4;
    const int row0 = blockIdx.x * 64;
    const int col0 = blockIdx.y * 64;

    const int fr = tid >> 2;
    const int fc = (tid & 3) * 4;

    float acc[4][4];
#pragma unroll
    for (int u = 0; u < 4; u++)
#pragma unroll
        for (int v = 0; v < 4; v++) acc[u][v] = 0.f;

    for (int k0 = 0; k0 < D_; k0 += 16) {
        {
            float4 av = *(const float4*)&g_A[(size_t)(row0 + fr)*D_ + k0 + fc];
            float4 wv = *(const float4*)&Wo [(size_t)(col0 + fr)*D_ + k0 + fc];
            As[fr][fc+0] = av.x; As[fr][fc+1] = av.y; As[fr][fc+2] = av.z; As[fr][fc+3] = av.w;
            Ws[fr][fc+0] = wv.x; Ws[fr][fc+1] = wv.y; Ws[fr][fc+2] = wv.z; Ws[fr][fc+3] = wv.w;
        }
        __syncthreads();
#pragma unroll
        for (int kk = 0; kk < 16; kk++) {
            float a4[4], w4[4];
#pragma unroll
            for (int u = 0; u < 4; u++) a4[u] = As[ty*4 + u][kk];
#pragma unroll
            for (int v = 0; v < 4; v++) w4[v] = Ws[tx*4 + v][kk];
#pragma unroll
            for (int u = 0; u < 4; u++)
#pragma unroll
                for (int v = 0; v < 4; v++) acc[u][v] += a4[u] * w4[v];
        }
        __syncthreads();
    }

#pragma unroll
    for (int u = 0; u < 4; u++) {
        int i = row0 + ty*4 + u;
#pragma unroll
        for (int v = 0; v < 4; v++) {
            int j = col0 + tx*4 + v;
            out[(size_t)i*D_ + j] = acc[u][v];
        }
    }
}

// ---------------------------------------------------------------------------
extern "C" void kernel_launch(void* const* d_in, const int* in_sizes, int n_in,
                              void* d_out, int out_size)
{
    const float* x  = (const float*)d_in[0];
    // d_in[1] = mask (causal tril; applied analytically)
    const float* Wq = (const float*)d_in[2];
    const float* Wk = (const float*)d_in[3];
    const float* Wv = (const float*)d_in[4];
    const float* Wo = (const float*)d_in[5];
    float* out = (float*)d_out;

    cudaFuncSetAttribute(flash_attn, cudaFuncAttributeMaxDynamicSharedMemorySize,
                         (int)FLASH_SMEM);

    dim3 g1(M_/64, D_/64);
    qkv_proj<<<g1, 256>>>(x, Wq, Wk, Wv);

    dim3 g2(S_/64, H_, B_);
    flash_attn<<<g2, 256, FLASH_SMEM>>>();

    dim3 g3(M_/64, D_/64);
    out_proj<<<g3, 256>>>(Wo, out);
}

// round 3
// speedup vs baseline: 3.0550x; 3.0550x over previous
#include <cuda_runtime.h>
#include <math.h>
#include <stdint.h>

#define B_  2
#define S_  2048
#define D_  1024
#define H_  16
#define HD_ 64
#define M_  (B_*S_)   // 4096

// Scratch (allocation-free rule)
__device__ float g_Q[B_*H_*S_*HD_];
__device__ float g_K[B_*H_*S_*HD_];
__device__ float g_V[B_*H_*S_*HD_];
__device__ float g_A[B_*S_*D_];

__device__ __forceinline__ uint32_t f2tf(float x) {
    uint32_t r;
    asm("cvt.rna.tf32.f32 %0, %1;" : "=r"(r) : "f"(x));
    return r;
}

// D += A(16x8,row) * B(8x8,col)  tf32
__device__ __forceinline__ void mma8(float d[4], const uint32_t a[4], const uint32_t b[2]) {
    asm volatile(
        "mma.sync.aligned.m16n8k8.row.col.f32.tf32.tf32.f32 "
        "{%0,%1,%2,%3}, {%4,%5,%6,%7}, {%8,%9}, {%0,%1,%2,%3};\n"
        : "+f"(d[0]), "+f"(d[1]), "+f"(d[2]), "+f"(d[3])
        : "r"(a[0]), "r"(a[1]), "r"(a[2]), "r"(a[3]), "r"(b[0]), "r"(b[1]));
}

// ---------------------------------------------------------------------------
// tf32 GEMM: C = A[M x 1024] @ W[1024 x 1024]^T   (y[m,n] = sum_k A[m,k]W[n,k])
// 128x128 CTA tile, 256 threads (8 warps as 4x2), warp tile 32x64, BK=32.
// permute=0: C_out[m*D+n] = v*scale.  permute=1: [b,h,s,hd] layout.
// ---------------------------------------------------------------------------
#define BM 128
#define BN 128
#define BK 32
#define SK 36   // smem row stride (uint32) -> conflict-free frags

__global__ __launch_bounds__(256) void gemm_tf32(const float* __restrict__ A,
                                                 const float* __restrict__ W,
                                                 float* __restrict__ C_out,
                                                 int permute, float scale)
{
    __shared__ uint32_t As[BM][SK];
    __shared__ uint32_t Bs[BN][SK];

    const int tid  = threadIdx.x;
    const int lane = tid & 31;
    const int warp = tid >> 5;
    const int g  = lane >> 2;   // 0..7
    const int t4 = lane & 3;    // 0..3
    const int wm = warp & 3;    // 0..3 -> m offset wm*32
    const int wn = warp >> 2;   // 0..1 -> n offset wn*64
    const int m_base = blockIdx.x * BM;
    const int n_base = blockIdx.y * BN;

    float acc[2][8][4];
#pragma unroll
    for (int ma = 0; ma < 2; ma++)
#pragma unroll
        for (int na = 0; na < 8; na++)
#pragma unroll
            for (int i = 0; i < 4; i++) acc[ma][na][i] = 0.f;

    for (int k0 = 0; k0 < D_; k0 += BK) {
        // stage: 128 rows x 32 k for both A and W, tf32-converted, STS.128
#pragma unroll
        for (int it = 0; it < 4; it++) {
            int f = tid + it * 256;       // 0..1023 float4 slots
            int c = (f & 7) * 4;          // k offset 0..28
            int r = f >> 3;               // row 0..127
            float4 av = *(const float4*)&A[(size_t)(m_base + r) * D_ + k0 + c];
            float4 wv = *(const float4*)&W[(size_t)(n_base + r) * D_ + k0 + c];
            uint4 au = make_uint4(f2tf(av.x), f2tf(av.y), f2tf(av.z), f2tf(av.w));
            uint4 wu = make_uint4(f2tf(wv.x), f2tf(wv.y), f2tf(wv.z), f2tf(wv.w));
            *(uint4*)&As[r][c] = au;
            *(uint4*)&Bs[r][c] = wu;
        }
        __syncthreads();

#pragma unroll
        for (int kk = 0; kk < BK; kk += 8) {
            uint32_t af[2][4];
#pragma unroll
            for (int ma = 0; ma < 2; ma++) {
                int row = wm * 32 + ma * 16;
                af[ma][0] = As[row + g][kk + t4];
                af[ma][1] = As[row + g + 8][kk + t4];
                af[ma][2] = As[row + g][kk + t4 + 4];
                af[ma][3] = As[row + g + 8][kk + t4 + 4];
            }
#pragma unroll
            for (int na = 0; na < 8; na++) {
                uint32_t bf[2];
                int col = wn * 64 + na * 8 + g;
                bf[0] = Bs[col][kk + t4];
                bf[1] = Bs[col][kk + t4 + 4];
                mma8(acc[0][na], af[0], bf);
                mma8(acc[1][na], af[1], bf);
            }
        }
        __syncthreads();
    }

    // epilogue
#pragma unroll
    for (int ma = 0; ma < 2; ma++) {
#pragma unroll
        for (int na = 0; na < 8; na++) {
            int m0 = m_base + wm * 32 + ma * 16 + g;
            int n0 = n_base + wn * 64 + na * 8 + 2 * t4;
#pragma unroll
            for (int i = 0; i < 4; i++) {
                int m = m0 + (i >> 1) * 8;
                int n = n0 + (i & 1);
                float v = acc[ma][na][i] * scale;
                if (permute) {
                    int b = m >> 11, s = m & 2047;
                    int h = n >> 6, hd = n & 63;
                    C_out[((size_t)(b * H_ + h) * S_ + s) * HD_ + hd] = v;
                } else {
                    C_out[(size_t)m * D_ + n] = v;
                }
            }
        }
    }
}

// ---------------------------------------------------------------------------
// Flash attention, tf32 mma. CTA = (b, h, 64-query tile), 128 threads/4 warps.
// Warp w owns query rows [w*16, w*16+16). 64-wide K/V tiles, causal skip.
// ---------------------------------------------------------------------------
#define FS 68
#define FLASH_SMEM (4 * 64 * FS * sizeof(uint32_t))

__global__ __launch_bounds__(128) void flash_mma()
{
    extern __shared__ uint32_t dynsm[];
    uint32_t (*Qs)[FS] = (uint32_t(*)[FS])(dynsm);
    uint32_t (*Ks)[FS] = (uint32_t(*)[FS])(dynsm + 1 * 64 * FS);
    uint32_t (*Vs)[FS] = (uint32_t(*)[FS])(dynsm + 2 * 64 * FS);
    uint32_t (*Ps)[FS] = (uint32_t(*)[FS])(dynsm + 3 * 64 * FS);

    const int t = blockIdx.x;
    const int h = blockIdx.y;
    const int b = blockIdx.z;
    const int tid  = threadIdx.x;
    const int lane = tid & 31;
    const int w    = tid >> 5;
    const int g  = lane >> 2;
    const int t4 = lane & 3;

    const float* Qp = g_Q + ((size_t)(b * H_ + h) * S_ + t * 64) * HD_;
    const float* Kp = g_K + ((size_t)(b * H_ + h) * S_) * HD_;
    const float* Vp = g_V + ((size_t)(b * H_ + h) * S_) * HD_;

    // stage Q (tf32)
#pragma unroll
    for (int it = 0; it < 8; it++) {
        int f = tid + it * 128;           // 0..1023 float4 slots
        int r = f >> 4, c = (f & 15) * 4;
        float4 qv = *(const float4*)&Qp[(size_t)r * HD_ + c];
        *(uint4*)&Qs[r][c] = make_uint4(f2tf(qv.x), f2tf(qv.y), f2tf(qv.z), f2tf(qv.w));
    }

    const float slope = exp2f(-0.5f * (float)(h + 1));
    const int qrA = t * 64 + w * 16 + g;      // this thread's row A
    const int qrB = qrA + 8;                  // row B

    float o[8][4];
#pragma unroll
    for (int da = 0; da < 8; da++)
#pragma unroll
        for (int i = 0; i < 4; i++) o[da][i] = 0.f;
    float mA = -INFINITY, mB = -INFINITY, lA = 0.f, lB = 0.f;

    __syncthreads();

    for (int j0 = 0; j0 <= t * 64; j0 += 64) {
        // stage K, V tiles (tf32)
#pragma unroll
        for (int it = 0; it < 8; it++) {
            int f = tid + it * 128;
            int r = f >> 4, c = (f & 15) * 4;
            float4 kv = *(const float4*)&Kp[(size_t)(j0 + r) * HD_ + c];
            float4 vv = *(const float4*)&Vp[(size_t)(j0 + r) * HD_ + c];
            *(uint4*)&Ks[r][c] = make_uint4(f2tf(kv.x), f2tf(kv.y), f2tf(kv.z), f2tf(kv.w));
            *(uint4*)&Vs[r][c] = make_uint4(f2tf(vv.x), f2tf(vv.y), f2tf(vv.z), f2tf(vv.w));
        }
        __syncthreads();

        // S = Q @ K^T  (warp tile 16x64)
        float s[8][4];
#pragma unroll
        for (int na = 0; na < 8; na++)
#pragma unroll
            for (int i = 0; i < 4; i++) s[na][i] = 0.f;

#pragma unroll
        for (int kk = 0; kk < 8; kk++) {
            uint32_t aq[4];
            aq[0] = Qs[w * 16 + g][kk * 8 + t4];
            aq[1] = Qs[w * 16 + g + 8][kk * 8 + t4];
            aq[2] = Qs[w * 16 + g][kk * 8 + t4 + 4];
            aq[3] = Qs[w * 16 + g + 8][kk * 8 + t4 + 4];
#pragma unroll
            for (int na = 0; na < 8; na++) {
                uint32_t bf[2];
                bf[0] = Ks[na * 8 + g][kk * 8 + t4];
                bf[1] = Ks[na * 8 + g][kk * 8 + t4 + 4];
                mma8(s[na], aq, bf);
            }
        }

        // ALiBi + causal mask on accum layout
        const bool diag = (j0 == t * 64);
#pragma unroll
        for (int na = 0; na < 8; na++) {
            int jc = j0 + na * 8 + 2 * t4;
            s[na][0] += slope * (float)(jc - qrA);
            s[na][1] += slope * (float)(jc + 1 - qrA);
            s[na][2] += slope * (float)(jc - qrB);
            s[na][3] += slope * (float)(jc + 1 - qrB);
            if (diag) {
                if (jc     > qrA) s[na][0] = -1e30f;
                if (jc + 1 > qrA) s[na][1] = -1e30f;
                if (jc     > qrB) s[na][2] = -1e30f;
                if (jc + 1 > qrB) s[na][3] = -1e30f;
            }
        }

        // online softmax (rows A: g, B: g+8); reduce over t4 lanes (xor 1,2)
        float mxA = -INFINITY, mxB = -INFINITY;
#pragma unroll
        for (int na = 0; na < 8; na++) {
            mxA = fmaxf(mxA, fmaxf(s[na][0], s[na][1]));
            mxB = fmaxf(mxB, fmaxf(s[na][2], s[na][3]));
        }
        mxA = fmaxf(mxA, __shfl_xor_sync(0xffffffffu, mxA, 1));
        mxA = fmaxf(mxA, __shfl_xor_sync(0xffffffffu, mxA, 2));
        mxB = fmaxf(mxB, __shfl_xor_sync(0xffffffffu, mxB, 1));
        mxB = fmaxf(mxB, __shfl_xor_sync(0xffffffffu, mxB, 2));

        float mnA = fmaxf(mA, mxA), mnB = fmaxf(mB, mxB);
        float aAl = __expf(mA - mnA), aBl = __expf(mB - mnB);
        mA = mnA; mB = mnB;

        float sumA = 0.f, sumB = 0.f;
#pragma unroll
        for (int na = 0; na < 8; na++) {
            s[na][0] = __expf(s[na][0] - mnA);
            s[na][1] = __expf(s[na][1] - mnA);
            s[na][2] = __expf(s[na][2] - mnB);
            s[na][3] = __expf(s[na][3] - mnB);
            sumA += s[na][0] + s[na][1];
            sumB += s[na][2] + s[na][3];
        }
        sumA += __shfl_xor_sync(0xffffffffu, sumA, 1);
        sumA += __shfl_xor_sync(0xffffffffu, sumA, 2);
        sumB += __shfl_xor_sync(0xffffffffu, sumB, 1);
        sumB += __shfl_xor_sync(0xffffffffu, sumB, 2);
        lA = lA * aAl + sumA;
        lB = lB * aBl + sumB;

#pragma unroll
        for (int da = 0; da < 8; da++) {
            o[da][0] *= aAl; o[da][1] *= aAl;
            o[da][2] *= aBl; o[da][3] *= aBl;
        }

        // P -> smem (per-warp-private rows) as tf32
#pragma unroll
        for (int na = 0; na < 8; na++) {
            int cc = na * 8 + 2 * t4;
            Ps[w * 16 + g][cc]         = f2tf(s[na][0]);
            Ps[w * 16 + g][cc + 1]     = f2tf(s[na][1]);
            Ps[w * 16 + g + 8][cc]     = f2tf(s[na][2]);
            Ps[w * 16 + g + 8][cc + 1] = f2tf(s[na][3]);
        }
        __syncwarp();

        // O += P @ V
#pragma unroll
        for (int kk = 0; kk < 8; kk++) {
            uint32_t ap[4];
            ap[0] = Ps[w * 16 + g][kk * 8 + t4];
            ap[1] = Ps[w * 16 + g + 8][kk * 8 + t4];
            ap[2] = Ps[w * 16 + g][kk * 8 + t4 + 4];
            ap[3] = Ps[w * 16 + g + 8][kk * 8 + t4 + 4];
#pragma unroll
            for (int da = 0; da < 8; da++) {
                uint32_t bf[2];
                bf[0] = Vs[kk * 8 + t4][da * 8 + g];
                bf[1] = Vs[kk * 8 + t4 + 4][da * 8 + g];
                mma8(o[da], ap, bf);
            }
        }
        __syncthreads();
    }

    // normalize + write [B,S,D]
    const float invA = 1.0f / lA, invB = 1.0f / lB;
#pragma unroll
    for (int da = 0; da < 8; da++) {
        int col = h * 64 + da * 8 + 2 * t4;
        size_t rA = ((size_t)b * S_ + qrA) * D_ + col;
        size_t rB = ((size_t)b * S_ + qrB) * D_ + col;
        g_A[rA]     = o[da][0] * invA;
        g_A[rA + 1] = o[da][1] * invA;
        g_A[rB]     = o[da][2] * invB;
        g_A[rB + 1] = o[da][3] * invB;
    }
}

// ---------------------------------------------------------------------------
extern "C" void kernel_launch(void* const* d_in, const int* in_sizes, int n_in,
                              void* d_out, int out_size)
{
    const float* x  = (const float*)d_in[0];
    // d_in[1] = causal mask, applied analytically
    const float* Wq = (const float*)d_in[2];
    const float* Wk = (const float*)d_in[3];
    const float* Wv = (const float*)d_in[4];
    const float* Wo = (const float*)d_in[5];
    float* out = (float*)d_out;

    float* q; cudaGetSymbolAddress((void**)&q, g_Q);
    float* k; cudaGetSymbolAddress((void**)&k, g_K);
    float* v; cudaGetSymbolAddress((void**)&v, g_V);
    float* a; cudaGetSymbolAddress((void**)&a, g_A);

    cudaFuncSetAttribute(flash_mma, cudaFuncAttributeMaxDynamicSharedMemorySize,
                         (int)FLASH_SMEM);

    dim3 gg(M_ / BM, D_ / BN);
    gemm_tf32<<<gg, 256>>>(x, Wq, q, 1, 0.125f);
    gemm_tf32<<<gg, 256>>>(x, Wk, k, 1, 1.0f);
    gemm_tf32<<<gg, 256>>>(x, Wv, v, 1, 1.0f);

    dim3 gf(S_ / 64, H_, B_);
    flash_mma<<<gf, 128, FLASH_SMEM>>>();

    gemm_tf32<<<gg, 256>>>(a, Wo, out, 0, 1.0f);
}

// round 4
// speedup vs baseline: 3.8705x; 1.2669x over previous
#include <cuda_runtime.h>
#include <math.h>
#include <stdint.h>

#define B_  2
#define S_  2048
#define D_  1024
#define H_  16
#define HD_ 64
#define M_  (B_*S_)   // 4096

// Scratch (allocation-free rule)
__device__ float g_Q[B_*H_*S_*HD_];
__device__ float g_K[B_*H_*S_*HD_];
__device__ float g_V[B_*H_*S_*HD_];
__device__ float g_A[B_*S_*D_];

__device__ __forceinline__ uint32_t f2tf(float x) {
    uint32_t r;
    asm("cvt.rna.tf32.f32 %0, %1;" : "=r"(r) : "f"(x));
    return r;
}

// D += A(16x8,row) * B(8x8,col)  tf32
__device__ __forceinline__ void mma8(float d[4], const uint32_t a[4], const uint32_t b[2]) {
    asm volatile(
        "mma.sync.aligned.m16n8k8.row.col.f32.tf32.tf32.f32 "
        "{%0,%1,%2,%3}, {%4,%5,%6,%7}, {%8,%9}, {%0,%1,%2,%3};\n"
        : "+f"(d[0]), "+f"(d[1]), "+f"(d[2]), "+f"(d[3])
        : "r"(a[0]), "r"(a[1]), "r"(a[2]), "r"(a[3]), "r"(b[0]), "r"(b[1]));
}

__device__ __forceinline__ void cpa16(uint32_t dst, const float* src) {
    asm volatile("cp.async.cg.shared.global [%0], [%1], 16;" :: "r"(dst), "l"(src));
}
__device__ __forceinline__ void cp_commit() { asm volatile("cp.async.commit_group;"); }
template<int N> __device__ __forceinline__ void cp_wait() {
    asm volatile("cp.async.wait_group %0;" :: "n"(N));
}

// ---------------------------------------------------------------------------
// tf32 GEMM mainloop: 128x128 CTA tile, 256 thr (8 warps 4x2), warp 32x64,
// BK=32, cp.async double-buffered, raw fp32 in smem, cvt at fragment load.
// ---------------------------------------------------------------------------
#define BM 128
#define BN 128
#define BK 32
#define SKG 36              // row stride (floats); 144B = 16B-aligned, conflict-free frags
#define GEMM_SMEM (2 * 2 * BM * SKG * sizeof(float))   // 73,728 B

__device__ __forceinline__ void gemm_main(const float* __restrict__ A,
                                          const float* __restrict__ W,
                                          int m_base, int n_base,
                                          float* sA, float* sB,
                                          uint32_t sA_u, uint32_t sB_u,
                                          float acc[2][8][4])
{
    const int tid  = threadIdx.x;
    const int lane = tid & 31;
    const int warp = tid >> 5;
    const int g  = lane >> 2;
    const int t4 = lane & 3;
    const int wm = warp & 3;
    const int wn = warp >> 2;

    auto stage = [&](int buf, int k0) {
#pragma unroll
        for (int it = 0; it < 4; it++) {
            int id = tid + it * 256;          // 1024 16B-chunks per operand
            int r  = id >> 3;
            int c4 = (id & 7) * 4;
            cpa16(sA_u + (uint32_t)((buf * BM + r) * SKG + c4) * 4u,
                  &A[(size_t)(m_base + r) * D_ + k0 + c4]);
            cpa16(sB_u + (uint32_t)((buf * BN + r) * SKG + c4) * 4u,
                  &W[(size_t)(n_base + r) * D_ + k0 + c4]);
        }
    };

    stage(0, 0);
    cp_commit();

    for (int ki = 0; ki < D_ / BK; ki++) {
        const int cur = ki & 1;
        if (ki + 1 < D_ / BK) {
            stage(cur ^ 1, (ki + 1) * BK);
            cp_commit();
            cp_wait<1>();
        } else {
            cp_wait<0>();
        }
        __syncthreads();

        const float* Ac = sA + cur * BM * SKG;
        const float* Bc = sB + cur * BN * SKG;
#pragma unroll
        for (int kk = 0; kk < BK; kk += 8) {
            uint32_t af[2][4];
#pragma unroll
            for (int ma = 0; ma < 2; ma++) {
                int row = wm * 32 + ma * 16;
                af[ma][0] = f2tf(Ac[(row + g)     * SKG + kk + t4]);
                af[ma][1] = f2tf(Ac[(row + g + 8) * SKG + kk + t4]);
                af[ma][2] = f2tf(Ac[(row + g)     * SKG + kk + t4 + 4]);
                af[ma][3] = f2tf(Ac[(row + g + 8) * SKG + kk + t4 + 4]);
            }
#pragma unroll
            for (int na = 0; na < 8; na++) {
                int col = wn * 64 + na * 8 + g;
                uint32_t bf[2];
                bf[0] = f2tf(Bc[col * SKG + kk + t4]);
                bf[1] = f2tf(Bc[col * SKG + kk + t4 + 4]);
                mma8(acc[0][na], af[0], bf);
                mma8(acc[1][na], af[1], bf);
            }
        }
        __syncthreads();
    }
}

// Fused QKV: blockIdx.y selects weight (y>>3) and n-tile (y&7).
__global__ __launch_bounds__(256, 2) void qkv_gemm(const float* __restrict__ x,
                                                   const float* __restrict__ Wq,
                                                   const float* __restrict__ Wk,
                                                   const float* __restrict__ Wv)
{
    extern __shared__ float sm[];
    float* sA = sm;
    float* sB = sm + 2 * BM * SKG;
    uint32_t sA_u = (uint32_t)__cvta_generic_to_shared(sA);
    uint32_t sB_u = (uint32_t)__cvta_generic_to_shared(sB);

    const int wsel = blockIdx.y >> 3;
    const float* W = (wsel == 0) ? Wq : (wsel == 1) ? Wk : Wv;
    float* Cout    = (wsel == 0) ? g_Q : (wsel == 1) ? g_K : g_V;
    const float scale = (wsel == 0) ? 0.125f : 1.0f;
    const int m_base = blockIdx.x * BM;
    const int n_base = (blockIdx.y & 7) * BN;

    float acc[2][8][4];
#pragma unroll
    for (int ma = 0; ma < 2; ma++)
#pragma unroll
        for (int na = 0; na < 8; na++)
#pragma unroll
            for (int i = 0; i < 4; i++) acc[ma][na][i] = 0.f;

    gemm_main(x, W, m_base, n_base, sA, sB, sA_u, sB_u, acc);

    const int lane = threadIdx.x & 31, warp = threadIdx.x >> 5;
    const int g = lane >> 2, t4 = lane & 3;
    const int wm = warp & 3, wn = warp >> 2;
#pragma unroll
    for (int ma = 0; ma < 2; ma++)
#pragma unroll
        for (int na = 0; na < 8; na++) {
            int m0 = m_base + wm * 32 + ma * 16 + g;
            int n0 = n_base + wn * 64 + na * 8 + 2 * t4;
#pragma unroll
            for (int i = 0; i < 4; i++) {
                int m = m0 + (i >> 1) * 8;
                int n = n0 + (i & 1);
                int b = m >> 11, s = m & 2047;
                int h = n >> 6, hd = n & 63;
                Cout[((size_t)(b * H_ + h) * S_ + s) * HD_ + hd] = acc[ma][na][i] * scale;
            }
        }
}

// Output projection: out = A @ Wo^T (plain layout)
__global__ __launch_bounds__(256, 2) void out_gemm(const float* __restrict__ Wo,
                                                   float* __restrict__ out)
{
    extern __shared__ float sm[];
    float* sA = sm;
    float* sB = sm + 2 * BM * SKG;
    uint32_t sA_u = (uint32_t)__cvta_generic_to_shared(sA);
    uint32_t sB_u = (uint32_t)__cvta_generic_to_shared(sB);

    const int m_base = blockIdx.x * BM;
    const int n_base = blockIdx.y * BN;

    float acc[2][8][4];
#pragma unroll
    for (int ma = 0; ma < 2; ma++)
#pragma unroll
        for (int na = 0; na < 8; na++)
#pragma unroll
            for (int i = 0; i < 4; i++) acc[ma][na][i] = 0.f;

    gemm_main(g_A, Wo, m_base, n_base, sA, sB, sA_u, sB_u, acc);

    const int lane = threadIdx.x & 31, warp = threadIdx.x >> 5;
    const int g = lane >> 2, t4 = lane & 3;
    const int wm = warp & 3, wn = warp >> 2;
#pragma unroll
    for (int ma = 0; ma < 2; ma++)
#pragma unroll
        for (int na = 0; na < 8; na++) {
            int m0 = m_base + wm * 32 + ma * 16 + g;
            int n0 = n_base + wn * 64 + na * 8 + 2 * t4;
#pragma unroll
            for (int i = 0; i < 4; i++) {
                int m = m0 + (i >> 1) * 8;
                int n = n0 + (i & 1);
                out[(size_t)m * D_ + n] = acc[ma][na][i];
            }
        }
}

// ---------------------------------------------------------------------------
// Flash attention, tf32 mma. CTA = (b, h, 128-query tile), 256 thr / 8 warps.
// Warp w owns q-rows [w*16, w*16+16). 64-wide K/V tiles, causal skip.
// smem: Qs[128][68] + Ks[64][68] + Vs[64][68] + Ps[128][68] = 104,448 B.
// ---------------------------------------------------------------------------
#define FS 68
#define FLASH_SMEM (384 * FS * sizeof(uint32_t))

__global__ __launch_bounds__(256, 2) void flash_mma()
{
    extern __shared__ uint32_t dynsm[];
    uint32_t (*Qs)[FS] = (uint32_t(*)[FS])(dynsm);
    uint32_t (*Ks)[FS] = (uint32_t(*)[FS])(dynsm + 128 * FS);
    uint32_t (*Vs)[FS] = (uint32_t(*)[FS])(dynsm + 192 * FS);
    uint32_t (*Ps)[FS] = (uint32_t(*)[FS])(dynsm + 256 * FS);

    const int t = (gridDim.x - 1) - blockIdx.x;   // heavy tiles first
    const int h = blockIdx.y;
    const int b = blockIdx.z;
    const int tid  = threadIdx.x;
    const int lane = tid & 31;
    const int w    = tid >> 5;
    const int g  = lane >> 2;
    const int t4 = lane & 3;

    const float* Qp = g_Q + ((size_t)(b * H_ + h) * S_ + t * 128) * HD_;
    const float* Kp = g_K + ((size_t)(b * H_ + h) * S_) * HD_;
    const float* Vp = g_V + ((size_t)(b * H_ + h) * S_) * HD_;

    // stage Q (tf32): 128x64 = 2048 float4
#pragma unroll
    for (int it = 0; it < 8; it++) {
        int f = tid + it * 256;
        int r = f >> 4, c = (f & 15) * 4;
        float4 qv = *(const float4*)&Qp[(size_t)r * HD_ + c];
        *(uint4*)&Qs[r][c] = make_uint4(f2tf(qv.x), f2tf(qv.y), f2tf(qv.z), f2tf(qv.w));
    }

    const float slope = exp2f(-0.5f * (float)(h + 1));
    const int qrA = t * 128 + w * 16 + g;
    const int qrB = qrA + 8;

    float o[8][4];
#pragma unroll
    for (int da = 0; da < 8; da++)
#pragma unroll
        for (int i = 0; i < 4; i++) o[da][i] = 0.f;
    float mA = -INFINITY, mB = -INFINITY, lA = 0.f, lB = 0.f;

    __syncthreads();

    const int j_end = t * 128 + 64;
    for (int j0 = 0; j0 <= j_end; j0 += 64) {
        // stage K, V (tf32): 2 x 64x64 = 2 x 1024 float4
#pragma unroll
        for (int it = 0; it < 4; it++) {
            int f = tid + it * 256;
            int r = f >> 4, c = (f & 15) * 4;
            float4 kv = *(const float4*)&Kp[(size_t)(j0 + r) * HD_ + c];
            float4 vv = *(const float4*)&Vp[(size_t)(j0 + r) * HD_ + c];
            *(uint4*)&Ks[r][c] = make_uint4(f2tf(kv.x), f2tf(kv.y), f2tf(kv.z), f2tf(kv.w));
            *(uint4*)&Vs[r][c] = make_uint4(f2tf(vv.x), f2tf(vv.y), f2tf(vv.z), f2tf(vv.w));
        }
        __syncthreads();

        // S = Q @ K^T (warp tile 16x64)
        float s[8][4];
#pragma unroll
        for (int na = 0; na < 8; na++)
#pragma unroll
            for (int i = 0; i < 4; i++) s[na][i] = 0.f;

#pragma unroll
        for (int kk = 0; kk < 8; kk++) {
            uint32_t aq[4];
            aq[0] = Qs[w * 16 + g][kk * 8 + t4];
            aq[1] = Qs[w * 16 + g + 8][kk * 8 + t4];
            aq[2] = Qs[w * 16 + g][kk * 8 + t4 + 4];
            aq[3] = Qs[w * 16 + g + 8][kk * 8 + t4 + 4];
#pragma unroll
            for (int na = 0; na < 8; na++) {
                uint32_t bf[2];
                bf[0] = Ks[na * 8 + g][kk * 8 + t4];
                bf[1] = Ks[na * 8 + g][kk * 8 + t4 + 4];
                mma8(s[na], aq, bf);
            }
        }

        // ALiBi + causal
        const bool nm = (j0 + 63) > (t * 128 + w * 16);
#pragma unroll
        for (int na = 0; na < 8; na++) {
            int jc = j0 + na * 8 + 2 * t4;
            s[na][0] += slope * (float)(jc - qrA);
            s[na][1] += slope * (float)(jc + 1 - qrA);
            s[na][2] += slope * (float)(jc - qrB);
            s[na][3] += slope * (float)(jc + 1 - qrB);
            if (nm) {
                if (jc     > qrA) s[na][0] = -1e30f;
                if (jc + 1 > qrA) s[na][1] = -1e30f;
                if (jc     > qrB) s[na][2] = -1e30f;
                if (jc + 1 > qrB) s[na][3] = -1e30f;
            }
        }

        // online softmax; reduce over t4 lanes (xor 1,2)
        float mxA = -INFINITY, mxB = -INFINITY;
#pragma unroll
        for (int na = 0; na < 8; na++) {
            mxA = fmaxf(mxA, fmaxf(s[na][0], s[na][1]));
            mxB = fmaxf(mxB, fmaxf(s[na][2], s[na][3]));
        }
        mxA = fmaxf(mxA, __shfl_xor_sync(0xffffffffu, mxA, 1));
        mxA = fmaxf(mxA, __shfl_xor_sync(0xffffffffu, mxA, 2));
        mxB = fmaxf(mxB, __shfl_xor_sync(0xffffffffu, mxB, 1));
        mxB = fmaxf(mxB, __shfl_xor_sync(0xffffffffu, mxB, 2));

        float mnA = fmaxf(mA, mxA), mnB = fmaxf(mB, mxB);
        float aAl = __expf(mA - mnA), aBl = __expf(mB - mnB);
        mA = mnA; mB = mnB;

        float sumA = 0.f, sumB = 0.f;
#pragma unroll
        for (int na = 0; na < 8; na++) {
            s[na][0] = __expf(s[na][0] - mnA);
            s[na][1] = __expf(s[na][1] - mnA);
            s[na][2] = __expf(s[na][2] - mnB);
            s[na][3] = __expf(s[na][3] - mnB);
            sumA += s[na][0] + s[na][1];
            sumB += s[na][2] + s[na][3];
        }
        sumA += __shfl_xor_sync(0xffffffffu, sumA, 1);
        sumA += __shfl_xor_sync(0xffffffffu, sumA, 2);
        sumB += __shfl_xor_sync(0xffffffffu, sumB, 1);
        sumB += __shfl_xor_sync(0xffffffffu, sumB, 2);
        lA = lA * aAl + sumA;
        lB = lB * aBl + sumB;

#pragma unroll
        for (int da = 0; da < 8; da++) {
            o[da][0] *= aAl; o[da][1] *= aAl;
            o[da][2] *= aBl; o[da][3] *= aBl;
        }

        // P -> smem (warp-private rows) as tf32
#pragma unroll
        for (int na = 0; na < 8; na++) {
            int cc = na * 8 + 2 * t4;
            Ps[w * 16 + g][cc]         = f2tf(s[na][0]);
            Ps[w * 16 + g][cc + 1]     = f2tf(s[na][1]);
            Ps[w * 16 + g + 8][cc]     = f2tf(s[na][2]);
            Ps[w * 16 + g + 8][cc + 1] = f2tf(s[na][3]);
        }
        __syncwarp();

        // O += P @ V
#pragma unroll
        for (int kk = 0; kk < 8; kk++) {
            uint32_t ap[4];
            ap[0] = Ps[w * 16 + g][kk * 8 + t4];
            ap[1] = Ps[w * 16 + g + 8][kk * 8 + t4];
            ap[2] = Ps[w * 16 + g][kk * 8 + t4 + 4];
            ap[3] = Ps[w * 16 + g + 8][kk * 8 + t4 + 4];
#pragma unroll
            for (int da = 0; da < 8; da++) {
                uint32_t bf[2];
                bf[0] = Vs[kk * 8 + t4][da * 8 + g];
                bf[1] = Vs[kk * 8 + t4 + 4][da * 8 + g];
                mma8(o[da], ap, bf);
            }
        }
        __syncthreads();
    }

    // normalize + write [B,S,D]
    const float invA = 1.0f / lA, invB = 1.0f / lB;
#pragma unroll
    for (int da = 0; da < 8; da++) {
        int col = h * 64 + da * 8 + 2 * t4;
        size_t rA = ((size_t)b * S_ + qrA) * D_ + col;
        size_t rB = ((size_t)b * S_ + qrB) * D_ + col;
        g_A[rA]     = o[da][0] * invA;
        g_A[rA + 1] = o[da][1] * invA;
        g_A[rB]     = o[da][2] * invB;
        g_A[rB + 1] = o[da][3] * invB;
    }
}

// ---------------------------------------------------------------------------
extern "C" void kernel_launch(void* const* d_in, const int* in_sizes, int n_in,
                              void* d_out, int out_size)
{
    const float* x  = (const float*)d_in[0];
    // d_in[1] = causal mask, applied analytically
    const float* Wq = (const float*)d_in[2];
    const float* Wk = (const float*)d_in[3];
    const float* Wv = (const float*)d_in[4];
    const float* Wo = (const float*)d_in[5];
    float* out = (float*)d_out;

    cudaFuncSetAttribute(qkv_gemm, cudaFuncAttributeMaxDynamicSharedMemorySize, (int)GEMM_SMEM);
    cudaFuncSetAttribute(out_gemm, cudaFuncAttributeMaxDynamicSharedMemorySize, (int)GEMM_SMEM);
    cudaFuncSetAttribute(flash_mma, cudaFuncAttributeMaxDynamicSharedMemorySize, (int)FLASH_SMEM);

    dim3 g1(M_ / BM, 24);                 // 3 weights x 8 n-tiles
    qkv_gemm<<<g1, 256, GEMM_SMEM>>>(x, Wq, Wk, Wv);

    dim3 g2(S_ / 128, H_, B_);
    flash_mma<<<g2, 256, FLASH_SMEM>>>();

    dim3 g3(M_ / BM, D_ / BN);
    out_gemm<<<g3, 256, GEMM_SMEM>>>(Wo, out);
}

// round 5
// speedup vs baseline: 4.3681x; 1.1286x over previous
#include <cuda_runtime.h>
#include <math.h>
#include <stdint.h>

#define B_  2
#define S_  2048
#define D_  1024
#define H_  16
#define HD_ 64
#define M_  (B_*S_)   // 4096
#define LOG2E 1.4426950408889634f

// Scratch (allocation-free rule)
__device__ float g_Q[B_*H_*S_*HD_];
__device__ float g_K[B_*H_*S_*HD_];
__device__ float g_V[B_*H_*S_*HD_];
__device__ float g_A[B_*S_*D_];
__device__ float g_xc[M_*D_];        // tf32-rounded x
__device__ float g_wc[4*D_*D_];      // tf32-rounded Wq,Wk,Wv,Wo

__device__ __forceinline__ uint32_t f2tf(float x) {
    uint32_t r;
    asm("cvt.rna.tf32.f32 %0, %1;" : "=r"(r) : "f"(x));
    return r;
}

// D += A(16x8,row) * B(8x8,col)  tf32
__device__ __forceinline__ void mma8(float d[4], const uint32_t a[4], const uint32_t b[2]) {
    asm volatile(
        "mma.sync.aligned.m16n8k8.row.col.f32.tf32.tf32.f32 "
        "{%0,%1,%2,%3}, {%4,%5,%6,%7}, {%8,%9}, {%0,%1,%2,%3};\n"
        : "+f"(d[0]), "+f"(d[1]), "+f"(d[2]), "+f"(d[3])
        : "r"(a[0]), "r"(a[1]), "r"(a[2]), "r"(a[3]), "r"(b[0]), "r"(b[1]));
}

__device__ __forceinline__ void cpa16(uint32_t dst, const float* src) {
    asm volatile("cp.async.cg.shared.global [%0], [%1], 16;" :: "r"(dst), "l"(src));
}
__device__ __forceinline__ void cp_commit() { asm volatile("cp.async.commit_group;"); }
template<int N> __device__ __forceinline__ void cp_wait() {
    asm volatile("cp.async.wait_group %0;" :: "n"(N));
}

// ---------------------------------------------------------------------------
// Pre-round x and the 4 weights to tf32 (rna). y=0: x, y=1..4: Wq,Wk,Wv,Wo.
// ---------------------------------------------------------------------------
__global__ __launch_bounds__(256) void precvt(const float* __restrict__ x,
                                              const float* __restrict__ Wq,
                                              const float* __restrict__ Wk,
                                              const float* __restrict__ Wv,
                                              const float* __restrict__ Wo)
{
    const int yy = blockIdx.y;
    const float* src; float* dst; int n4;
    if (yy == 0)      { src = x;  dst = g_xc;              n4 = M_*D_/4; }
    else if (yy == 1) { src = Wq; dst = g_wc;              n4 = D_*D_/4; }
    else if (yy == 2) { src = Wk; dst = g_wc + 1*D_*D_;    n4 = D_*D_/4; }
    else if (yy == 3) { src = Wv; dst = g_wc + 2*D_*D_;    n4 = D_*D_/4; }
    else              { src = Wo; dst = g_wc + 3*D_*D_;    n4 = D_*D_/4; }
#pragma unroll
    for (int it = 0; it < 4; it++) {
        int i = (blockIdx.x * 256 + threadIdx.x) + it * 256 * gridDim.x;
        if (i < n4) {
            float4 v = ((const float4*)src)[i];
            uint4 u = make_uint4(f2tf(v.x), f2tf(v.y), f2tf(v.z), f2tf(v.w));
            ((uint4*)dst)[i] = u;
        }
    }
}

// ---------------------------------------------------------------------------
// tf32 GEMM mainloop: 128x128 CTA, 256 thr (8 warps 4x2), warp 32x64, BK=32,
// cp.async double-buffered. Inputs are pre-rounded tf32 bits: no cvt here.
// ---------------------------------------------------------------------------
#define BM 128
#define BN 128
#define BK 32
#define SKG 36
#define GEMM_SMEM (2 * 2 * BM * SKG * sizeof(float))   // 73,728 B

__device__ __forceinline__ void gemm_main(const float* __restrict__ A,
                                          const float* __restrict__ W,
                                          int m_base, int n_base,
                                          const uint32_t* sA, const uint32_t* sB,
                                          uint32_t sA_u, uint32_t sB_u,
                                          float acc[2][8][4])
{
    const int tid  = threadIdx.x;
    const int lane = tid & 31;
    const int warp = tid >> 5;
    const int g  = lane >> 2;
    const int t4 = lane & 3;
    const int wm = warp & 3;
    const int wn = warp >> 2;

    auto stage = [&](int buf, int k0) {
#pragma unroll
        for (int it = 0; it < 4; it++) {
            int id = tid + it * 256;
            int r  = id >> 3;
            int c4 = (id & 7) * 4;
            cpa16(sA_u + (uint32_t)((buf * BM + r) * SKG + c4) * 4u,
                  &A[(size_t)(m_base + r) * D_ + k0 + c4]);
            cpa16(sB_u + (uint32_t)((buf * BN + r) * SKG + c4) * 4u,
                  &W[(size_t)(n_base + r) * D_ + k0 + c4]);
        }
    };

    stage(0, 0);
    cp_commit();

    for (int ki = 0; ki < D_ / BK; ki++) {
        const int cur = ki & 1;
        if (ki + 1 < D_ / BK) {
            stage(cur ^ 1, (ki + 1) * BK);
            cp_commit();
            cp_wait<1>();
        } else {
            cp_wait<0>();
        }
        __syncthreads();

        const uint32_t* Ac = sA + cur * BM * SKG;
        const uint32_t* Bc = sB + cur * BN * SKG;
#pragma unroll
        for (int kk = 0; kk < BK; kk += 8) {
            uint32_t af[2][4];
#pragma unroll
            for (int ma = 0; ma < 2; ma++) {
                int row = wm * 32 + ma * 16;
                af[ma][0] = Ac[(row + g)     * SKG + kk + t4];
                af[ma][1] = Ac[(row + g + 8) * SKG + kk + t4];
                af[ma][2] = Ac[(row + g)     * SKG + kk + t4 + 4];
                af[ma][3] = Ac[(row + g + 8) * SKG + kk + t4 + 4];
            }
#pragma unroll
            for (int na = 0; na < 8; na++) {
                int col = wn * 64 + na * 8 + g;
                uint32_t bf[2];
                bf[0] = Bc[col * SKG + kk + t4];
                bf[1] = Bc[col * SKG + kk + t4 + 4];
                mma8(acc[0][na], af[0], bf);
                mma8(acc[1][na], af[1], bf);
            }
        }
        __syncthreads();
    }
}

// Fused QKV. Q scaled by 0.125*log2e; outputs stored tf32-rounded.
__global__ __launch_bounds__(256, 2) void qkv_gemm()
{
    extern __shared__ float sm[];
    const uint32_t* sA = (const uint32_t*)sm;
    const uint32_t* sB = (const uint32_t*)(sm + 2 * BM * SKG);
    uint32_t sA_u = (uint32_t)__cvta_generic_to_shared(sm);
    uint32_t sB_u = (uint32_t)__cvta_generic_to_shared(sm + 2 * BM * SKG);

    const int wsel = blockIdx.y >> 3;
    const float* W = g_wc + (size_t)wsel * D_ * D_;
    float* Cout    = (wsel == 0) ? g_Q : (wsel == 1) ? g_K : g_V;
    const float scale = (wsel == 0) ? (0.125f * LOG2E) : 1.0f;
    const int m_base = blockIdx.x * BM;
    const int n_base = (blockIdx.y & 7) * BN;

    float acc[2][8][4];
#pragma unroll
    for (int ma = 0; ma < 2; ma++)
#pragma unroll
        for (int na = 0; na < 8; na++)
#pragma unroll
            for (int i = 0; i < 4; i++) acc[ma][na][i] = 0.f;

    gemm_main(g_xc, W, m_base, n_base, sA, sB, sA_u, sB_u, acc);

    const int lane = threadIdx.x & 31, warp = threadIdx.x >> 5;
    const int g = lane >> 2, t4 = lane & 3;
    const int wm = warp & 3, wn = warp >> 2;
#pragma unroll
    for (int ma = 0; ma < 2; ma++)
#pragma unroll
        for (int na = 0; na < 8; na++) {
            int m0 = m_base + wm * 32 + ma * 16 + g;
            int n0 = n_base + wn * 64 + na * 8 + 2 * t4;
#pragma unroll
            for (int i = 0; i < 4; i++) {
                int m = m0 + (i >> 1) * 8;
                int n = n0 + (i & 1);
                int b = m >> 11, s = m & 2047;
                int h = n >> 6, hd = n & 63;
                uint32_t bits = f2tf(acc[ma][na][i] * scale);
                ((uint32_t*)Cout)[((size_t)(b * H_ + h) * S_ + s) * HD_ + hd] = bits;
            }
        }
}

// Output projection: out = A @ Wo^T (fp32 output, no rounding)
__global__ __launch_bounds__(256, 2) void out_gemm(float* __restrict__ out)
{
    extern __shared__ float sm[];
    const uint32_t* sA = (const uint32_t*)sm;
    const uint32_t* sB = (const uint32_t*)(sm + 2 * BM * SKG);
    uint32_t sA_u = (uint32_t)__cvta_generic_to_shared(sm);
    uint32_t sB_u = (uint32_t)__cvta_generic_to_shared(sm + 2 * BM * SKG);

    const int m_base = blockIdx.x * BM;
    const int n_base = blockIdx.y * BN;

    float acc[2][8][4];
#pragma unroll
    for (int ma = 0; ma < 2; ma++)
#pragma unroll
        for (int na = 0; na < 8; na++)
#pragma unroll
            for (int i = 0; i < 4; i++) acc[ma][na][i] = 0.f;

    gemm_main(g_A, g_wc + 3 * D_ * D_, m_base, n_base, sA, sB, sA_u, sB_u, acc);

    const int lane = threadIdx.x & 31, warp = threadIdx.x >> 5;
    const int g = lane >> 2, t4 = lane & 3;
    const int wm = warp & 3, wn = warp >> 2;
#pragma unroll
    for (int ma = 0; ma < 2; ma++)
#pragma unroll
        for (int na = 0; na < 8; na++) {
            int m0 = m_base + wm * 32 + ma * 16 + g;
            int n0 = n_base + wn * 64 + na * 8 + 2 * t4;
#pragma unroll
            for (int i = 0; i < 4; i++) {
                int m = m0 + (i >> 1) * 8;
                int n = n0 + (i & 1);
                out[(size_t)m * D_ + n] = acc[ma][na][i];
            }
        }
}

// ---------------------------------------------------------------------------
// Flash attention. CTA = (b,h,128-q-tile), 256 thr / 8 warps, warp = 16 rows.
// Double-buffered cp.async K/V. P transposed C->A layout via quad shuffles
// (no Ps smem). exp2-domain softmax (log2e pre-folded into Q and slope).
// smem: Qs[128][68] + Ks[2][64][68] + Vs[2][64][72] = 106,496 B.
// ---------------------------------------------------------------------------
#define FSQ 68
#define FSV 72
#define OFF_K (128 * FSQ)
#define OFF_V (OFF_K + 2 * 64 * FSQ)
#define FLASH_SMEM ((OFF_V + 2 * 64 * FSV) * sizeof(uint32_t))

__global__ __launch_bounds__(256, 2) void flash_mma()
{
    extern __shared__ uint32_t dynsm[];
    uint32_t (*Qs)[FSQ] = (uint32_t(*)[FSQ])(dynsm);
    uint32_t (*Ks)[FSQ] = (uint32_t(*)[FSQ])(dynsm + OFF_K);   // [2*64][FSQ]
    uint32_t (*Vs)[FSV] = (uint32_t(*)[FSV])(dynsm + OFF_V);   // [2*64][FSV]
    const uint32_t smem_base = (uint32_t)__cvta_generic_to_shared(dynsm);

    const int t = (gridDim.x - 1) - blockIdx.x;   // heavy tiles first
    const int h = blockIdx.y;
    const int b = blockIdx.z;
    const int tid  = threadIdx.x;
    const int lane = tid & 31;
    const int w    = tid >> 5;
    const int g  = lane >> 2;
    const int t4 = lane & 3;
    const int src_lo = (lane & 28) | (t4 >> 1);
    const int src_hi = src_lo + 2;
    const bool odd = (t4 & 1);

    const float* Qp = g_Q + ((size_t)(b * H_ + h) * S_ + t * 128) * HD_;
    const float* Kp = g_K + ((size_t)(b * H_ + h) * S_) * HD_;
    const float* Vp = g_V + ((size_t)(b * H_ + h) * S_) * HD_;

    // prologue: stage Q + first K/V tile (group 0)
#pragma unroll
    for (int it = 0; it < 8; it++) {
        int f = tid + it * 256;             // 2048 float4
        int r = f >> 4, c = (f & 15) * 4;
        cpa16(smem_base + (uint32_t)(r * FSQ + c) * 4u, &Qp[(size_t)r * HD_ + c]);
    }
#pragma unroll
    for (int it = 0; it < 4; it++) {
        int f = tid + it * 256;             // 1024 float4
        int r = f >> 4, c = (f & 15) * 4;
        cpa16(smem_base + (uint32_t)(OFF_K + r * FSQ + c) * 4u, &Kp[(size_t)r * HD_ + c]);
        cpa16(smem_base + (uint32_t)(OFF_V + r * FSV + c) * 4u, &Vp[(size_t)r * HD_ + c]);
    }
    cp_commit();

    const float slope2 = exp2f(-0.5f * (float)(h + 1)) * LOG2E;
    const int qrA = t * 128 + w * 16 + g;
    const int qrB = qrA + 8;

    float o[8][4];
#pragma unroll
    for (int da = 0; da < 8; da++)
#pragma unroll
        for (int i = 0; i < 4; i++) o[da][i] = 0.f;
    float mA = -INFINITY, mB = -INFINITY, lA = 0.f, lB = 0.f;

    const int j_end = t * 128 + 64;
    for (int j0 = 0; j0 <= j_end; j0 += 64) {
        const int cur = (j0 >> 6) & 1;
        if (j0 + 64 <= j_end) {
            const int nb = cur ^ 1;
#pragma unroll
            for (int it = 0; it < 4; it++) {
                int f = tid + it * 256;
                int r = f >> 4, c = (f & 15) * 4;
                cpa16(smem_base + (uint32_t)(OFF_K + (nb * 64 + r) * FSQ + c) * 4u,
                      &Kp[(size_t)(j0 + 64 + r) * HD_ + c]);
                cpa16(smem_base + (uint32_t)(OFF_V + (nb * 64 + r) * FSV + c) * 4u,
                      &Vp[(size_t)(j0 + 64 + r) * HD_ + c]);
            }
            cp_commit();
            cp_wait<1>();
        } else {
            cp_wait<0>();
        }
        __syncthreads();

        const uint32_t (*Kc)[FSQ] = Ks + cur * 64;
        const uint32_t (*Vc)[FSV] = Vs + cur * 64;

        // S = Q @ K^T (warp tile 16x64)
        float s[8][4];
#pragma unroll
        for (int na = 0; na < 8; na++)
#pragma unroll
            for (int i = 0; i < 4; i++) s[na][i] = 0.f;

#pragma unroll
        for (int kk = 0; kk < 8; kk++) {
            uint32_t aq[4];
            aq[0] = Qs[w * 16 + g][kk * 8 + t4];
            aq[1] = Qs[w * 16 + g + 8][kk * 8 + t4];
            aq[2] = Qs[w * 16 + g][kk * 8 + t4 + 4];
            aq[3] = Qs[w * 16 + g + 8][kk * 8 + t4 + 4];
#pragma unroll
            for (int na = 0; na < 8; na++) {
                uint32_t bf[2];
                bf[0] = Kc[na * 8 + g][kk * 8 + t4];
                bf[1] = Kc[na * 8 + g][kk * 8 + t4 + 4];
                mma8(s[na], aq, bf);
            }
        }

        // ALiBi (base-2) + causal
        const bool nm = (j0 + 63) > (t * 128 + w * 16);
#pragma unroll
        for (int na = 0; na < 8; na++) {
            int jc = j0 + na * 8 + 2 * t4;
            s[na][0] += slope2 * (float)(jc - qrA);
            s[na][1] += slope2 * (float)(jc + 1 - qrA);
            s[na][2] += slope2 * (float)(jc - qrB);
            s[na][3] += slope2 * (float)(jc + 1 - qrB);
            if (nm) {
                if (jc     > qrA) s[na][0] = -1e30f;
                if (jc + 1 > qrA) s[na][1] = -1e30f;
                if (jc     > qrB) s[na][2] = -1e30f;
                if (jc + 1 > qrB) s[na][3] = -1e30f;
            }
        }

        // online softmax in base-2; reduce over t4 lanes
        float mxA = -INFINITY, mxB = -INFINITY;
#pragma unroll
        for (int na = 0; na < 8; na++) {
            mxA = fmaxf(mxA, fmaxf(s[na][0], s[na][1]));
            mxB = fmaxf(mxB, fmaxf(s[na][2], s[na][3]));
        }
        mxA = fmaxf(mxA, __shfl_xor_sync(0xffffffffu, mxA, 1));
        mxA = fmaxf(mxA, __shfl_xor_sync(0xffffffffu, mxA, 2));
        mxB = fmaxf(mxB, __shfl_xor_sync(0xffffffffu, mxB, 1));
        mxB = fmaxf(mxB, __shfl_xor_sync(0xffffffffu, mxB, 2));

        float mnA = fmaxf(mA, mxA), mnB = fmaxf(mB, mxB);
        float aAl = exp2f(mA - mnA), aBl = exp2f(mB - mnB);
        mA = mnA; mB = mnB;

        float sumA = 0.f, sumB = 0.f;
#pragma unroll
        for (int na = 0; na < 8; na++) {
            s[na][0] = exp2f(s[na][0] - mnA);
            s[na][1] = exp2f(s[na][1] - mnA);
            s[na][2] = exp2f(s[na][2] - mnB);
            s[na][3] = exp2f(s[na][3] - mnB);
            sumA += s[na][0] + s[na][1];
            sumB += s[na][2] + s[na][3];
        }
        sumA += __shfl_xor_sync(0xffffffffu, sumA, 1);
        sumA += __shfl_xor_sync(0xffffffffu, sumA, 2);
        sumB += __shfl_xor_sync(0xffffffffu, sumB, 1);
        sumB += __shfl_xor_sync(0xffffffffu, sumB, 2);
        lA = lA * aAl + sumA;
        lB = lB * aBl + sumB;

#pragma unroll
        for (int da = 0; da < 8; da++) {
            o[da][0] *= aAl; o[da][1] *= aAl;
            o[da][2] *= aBl; o[da][3] *= aBl;
        }

        // round P to tf32 in place (bits kept in float regs)
#pragma unroll
        for (int na = 0; na < 8; na++)
#pragma unroll
            for (int i = 0; i < 4; i++)
                s[na][i] = __uint_as_float(f2tf(s[na][i]));

        // O += P @ V ; P A-fragments via quad shuffles (C->A col redistribute)
#pragma unroll
        for (int kk = 0; kk < 8; kk++) {
            float v00 = __shfl_sync(0xffffffffu, s[kk][0], src_lo);
            float v01 = __shfl_sync(0xffffffffu, s[kk][1], src_lo);
            float v10 = __shfl_sync(0xffffffffu, s[kk][2], src_lo);
            float v11 = __shfl_sync(0xffffffffu, s[kk][3], src_lo);
            float w00 = __shfl_sync(0xffffffffu, s[kk][0], src_hi);
            float w01 = __shfl_sync(0xffffffffu, s[kk][1], src_hi);
            float w10 = __shfl_sync(0xffffffffu, s[kk][2], src_hi);
            float w11 = __shfl_sync(0xffffffffu, s[kk][3], src_hi);
            uint32_t ap[4];
            ap[0] = __float_as_uint(odd ? v01 : v00);
            ap[1] = __float_as_uint(odd ? v11 : v10);
            ap[2] = __float_as_uint(odd ? w01 : w00);
            ap[3] = __float_as_uint(odd ? w11 : w10);
#pragma unroll
            for (int da = 0; da < 8; da++) {
                uint32_t bf[2];
                bf[0] = Vc[kk * 8 + t4][da * 8 + g];
                bf[1] = Vc[kk * 8 + t4 + 4][da * 8 + g];
                mma8(o[da], ap, bf);
            }
        }
        __syncthreads();
    }

    // normalize + write [B,S,D] (tf32-rounded for out_gemm)
    const float invA = 1.0f / lA, invB = 1.0f / lB;
    uint32_t* Aout = (uint32_t*)g_A;
#pragma unroll
    for (int da = 0; da < 8; da++) {
        int col = h * 64 + da * 8 + 2 * t4;
        size_t rA = ((size_t)b * S_ + qrA) * D_ + col;
        size_t rB = ((size_t)b * S_ + qrB) * D_ + col;
        Aout[rA]     = f2tf(o[da][0] * invA);
        Aout[rA + 1] = f2tf(o[da][1] * invA);
        Aout[rB]     = f2tf(o[da][2] * invB);
        Aout[rB + 1] = f2tf(o[da][3] * invB);
    }
}

// ---------------------------------------------------------------------------
extern "C" void kernel_launch(void* const* d_in, const int* in_sizes, int n_in,
                              void* d_out, int out_size)
{
    const float* x  = (const float*)d_in[0];
    // d_in[1] = causal mask, applied analytically
    const float* Wq = (const float*)d_in[2];
    const float* Wk = (const float*)d_in[3];
    const float* Wv = (const float*)d_in[4];
    const float* Wo = (const float*)d_in[5];
    float* out = (float*)d_out;

    cudaFuncSetAttribute(qkv_gemm, cudaFuncAttributeMaxDynamicSharedMemorySize, (int)GEMM_SMEM);
    cudaFuncSetAttribute(out_gemm, cudaFuncAttributeMaxDynamicSharedMemorySize, (int)GEMM_SMEM);
    cudaFuncSetAttribute(flash_mma, cudaFuncAttributeMaxDynamicSharedMemorySize, (int)FLASH_SMEM);

    dim3 g0(1024, 5);
    precvt<<<g0, 256>>>(x, Wq, Wk, Wv, Wo);

    dim3 g1(M_ / BM, 24);                 // 3 weights x 8 n-tiles
    qkv_gemm<<<g1, 256, GEMM_SMEM>>>();

    dim3 g2(S_ / 128, H_, B_);
    flash_mma<<<g2, 256, FLASH_SMEM>>>();

    dim3 g3(M_ / BM, D_ / BN);
    out_gemm<<<g3, 256, GEMM_SMEM>>>(out);
}

// round 9
// speedup vs baseline: 4.6868x; 1.0730x over previous
#include <cuda_runtime.h>
#include <math.h>
#include <stdint.h>

#define B_  2
#define S_  2048
#define D_  1024
#define H_  16
#define HD_ 64
#define M_  (B_*S_)   // 4096
#define LOG2E 1.4426950408889634f

// Scratch (allocation-free rule)
__device__ float g_Q[B_*H_*S_*HD_];
__device__ float g_K[B_*H_*S_*HD_];
__device__ float g_V[B_*H_*HD_*S_];   // TRANSPOSED: [b,h,hd,s]
__device__ float g_A[B_*S_*D_];
__device__ float g_xc[M_*D_];         // tf32-rounded x
__device__ float g_wc[4*D_*D_];       // tf32-rounded Wq,Wk,Wv,Wo

__device__ __forceinline__ uint32_t f2tf(float x) {
    uint32_t r;
    asm("cvt.rna.tf32.f32 %0, %1;" : "=r"(r) : "f"(x));
    return r;
}

// D += A(16x8,row) * B(8x8,col)  tf32
__device__ __forceinline__ void mma8(float d[4], const uint32_t a[4], const uint32_t b[2]) {
    asm volatile(
        "mma.sync.aligned.m16n8k8.row.col.f32.tf32.tf32.f32 "
        "{%0,%1,%2,%3}, {%4,%5,%6,%7}, {%8,%9}, {%0,%1,%2,%3};\n"
        : "+f"(d[0]), "+f"(d[1]), "+f"(d[2]), "+f"(d[3])
        : "r"(a[0]), "r"(a[1]), "r"(a[2]), "r"(a[3]), "r"(b[0]), "r"(b[1]));
}

__device__ __forceinline__ void cpa16(uint32_t dst, const float* src) {
    asm volatile("cp.async.cg.shared.global [%0], [%1], 16;" :: "r"(dst), "l"(src));
}
__device__ __forceinline__ void cp_commit() { asm volatile("cp.async.commit_group;"); }
template<int N> __device__ __forceinline__ void cp_wait() {
    asm volatile("cp.async.wait_group %0;" :: "n"(N));
}

// ---------------------------------------------------------------------------
// Pre-round x and 4 weights to tf32 (rna)
// ---------------------------------------------------------------------------
__global__ __launch_bounds__(256) void precvt(const float* __restrict__ x,
                                              const float* __restrict__ Wq,
                                              const float* __restrict__ Wk,
                                              const float* __restrict__ Wv,
                                              const float* __restrict__ Wo)
{
    const int yy = blockIdx.y;
    const float* src; float* dst; int n4;
    if (yy == 0)      { src = x;  dst = g_xc;           n4 = M_*D_/4; }
    else if (yy == 1) { src = Wq; dst = g_wc;           n4 = D_*D_/4; }
    else if (yy == 2) { src = Wk; dst = g_wc + 1*D_*D_; n4 = D_*D_/4; }
    else if (yy == 3) { src = Wv; dst = g_wc + 2*D_*D_; n4 = D_*D_/4; }
    else              { src = Wo; dst = g_wc + 3*D_*D_; n4 = D_*D_/4; }
#pragma unroll
    for (int it = 0; it < 4; it++) {
        int i = (blockIdx.x * 256 + threadIdx.x) + it * 256 * gridDim.x;
        if (i < n4) {
            float4 v = ((const float4*)src)[i];
            ((uint4*)dst)[i] = make_uint4(f2tf(v.x), f2tf(v.y), f2tf(v.z), f2tf(v.w));
        }
    }
}

// ---------------------------------------------------------------------------
// tf32 GEMM: 128x128 CTA, 256 thr (8 warps 4x2), warp 32x64, BK=32,
// cp.async double-buffered, float2 fragment loads via k-relabel.
// ---------------------------------------------------------------------------
#define BM 128
#define BN 128
#define BK 32
#define SKG 40              // 160B stride -> conflict-free float2 frags
#define GEMM_SMEM (2 * 2 * BM * SKG * sizeof(float))   // 81,920 B

__device__ __forceinline__ void gemm_main(const float* __restrict__ A,
                                          const float* __restrict__ W,
                                          int m_base, int n_base,
                                          const float* sA, const float* sB,
                                          uint32_t sA_u, uint32_t sB_u,
                                          float acc[2][8][4])
{
    const int tid  = threadIdx.x;
    const int lane = tid & 31;
    const int warp = tid >> 5;
    const int g  = lane >> 2;
    const int t4 = lane & 3;
    const int wm = warp & 3;
    const int wn = warp >> 2;

    auto stage = [&](int buf, int k0) {
#pragma unroll
        for (int it = 0; it < 4; it++) {
            int id = tid + it * 256;
            int r  = id >> 3;
            int c4 = (id & 7) * 4;
            cpa16(sA_u + (uint32_t)((buf * BM + r) * SKG + c4) * 4u,
                  &A[(size_t)(m_base + r) * D_ + k0 + c4]);
            cpa16(sB_u + (uint32_t)((buf * BN + r) * SKG + c4) * 4u,
                  &W[(size_t)(n_base + r) * D_ + k0 + c4]);
        }
    };

    stage(0, 0);
    cp_commit();

    for (int ki = 0; ki < D_ / BK; ki++) {
        const int cur = ki & 1;
        if (ki + 1 < D_ / BK) {
            stage(cur ^ 1, (ki + 1) * BK);
            cp_commit();
            cp_wait<1>();
        } else {
            cp_wait<0>();
        }
        __syncthreads();

        const float* Ac = sA + cur * BM * SKG;
        const float* Bc = sB + cur * BN * SKG;
#pragma unroll
        for (int kk = 0; kk < BK; kk += 8) {
            uint32_t af[2][4];
#pragma unroll
            for (int ma = 0; ma < 2; ma++) {
                int row = wm * 32 + ma * 16;
                float2 lo = *(const float2*)&Ac[(row + g)     * SKG + kk + 2 * t4];
                float2 hi = *(const float2*)&Ac[(row + g + 8) * SKG + kk + 2 * t4];
                af[ma][0] = __float_as_uint(lo.x);
                af[ma][1] = __float_as_uint(hi.x);
                af[ma][2] = __float_as_uint(lo.y);
                af[ma][3] = __float_as_uint(hi.y);
            }
#pragma unroll
            for (int na = 0; na < 8; na++) {
                int col = wn * 64 + na * 8 + g;
                float2 bv = *(const float2*)&Bc[col * SKG + kk + 2 * t4];
                uint32_t bf[2] = { __float_as_uint(bv.x), __float_as_uint(bv.y) };
                mma8(acc[0][na], af[0], bf);
                mma8(acc[1][na], af[1], bf);
            }
        }
        __syncthreads();
    }
}

// Fused QKV. Q scaled by 0.125*log2e; V stored transposed [b,h,hd,s].
__global__ __launch_bounds__(256, 2) void qkv_gemm()
{
    extern __shared__ float sm[];
    const float* sA = sm;
    const float* sB = sm + 2 * BM * SKG;
    uint32_t sA_u = (uint32_t)__cvta_generic_to_shared(sm);
    uint32_t sB_u = (uint32_t)__cvta_generic_to_shared(sm + 2 * BM * SKG);

    const int wsel = blockIdx.y >> 3;
    const float* W = g_wc + (size_t)wsel * D_ * D_;
    float* Cout    = (wsel == 0) ? g_Q : (wsel == 1) ? g_K : g_V;
    const float scale = (wsel == 0) ? (0.125f * LOG2E) : 1.0f;
    const int m_base = blockIdx.x * BM;
    const int n_base = (blockIdx.y & 7) * BN;

    float acc[2][8][4];
#pragma unroll
    for (int ma = 0; ma < 2; ma++)
#pragma unroll
        for (int na = 0; na < 8; na++)
#pragma unroll
            for (int i = 0; i < 4; i++) acc[ma][na][i] = 0.f;

    gemm_main(g_xc, W, m_base, n_base, sA, sB, sA_u, sB_u, acc);

    const int lane = threadIdx.x & 31, warp = threadIdx.x >> 5;
    const int g = lane >> 2, t4 = lane & 3;
    const int wm = warp & 3, wn = warp >> 2;
#pragma unroll
    for (int ma = 0; ma < 2; ma++)
#pragma unroll
        for (int na = 0; na < 8; na++) {
            int m0 = m_base + wm * 32 + ma * 16 + g;
            int n0 = n_base + wn * 64 + na * 8 + 2 * t4;
#pragma unroll
            for (int i = 0; i < 4; i++) {
                int m = m0 + (i >> 1) * 8;
                int n = n0 + (i & 1);
                int b = m >> 11, s = m & 2047;
                int h = n >> 6, hd = n & 63;
                uint32_t bits = f2tf(acc[ma][na][i] * scale);
                size_t idx;
                if (wsel == 2)  // V transposed: [b,h,hd,s]
                    idx = ((size_t)(b * H_ + h) * HD_ + hd) * S_ + s;
                else
                    idx = ((size_t)(b * H_ + h) * S_ + s) * HD_ + hd;
                ((uint32_t*)Cout)[idx] = bits;
            }
        }
}

// Output projection: out = A @ Wo^T (fp32 output)
__global__ __launch_bounds__(256, 2) void out_gemm(float* __restrict__ out)
{
    extern __shared__ float sm[];
    const float* sA = sm;
    const float* sB = sm + 2 * BM * SKG;
    uint32_t sA_u = (uint32_t)__cvta_generic_to_shared(sm);
    uint32_t sB_u = (uint32_t)__cvta_generic_to_shared(sm + 2 * BM * SKG);

    const int m_base = blockIdx.x * BM;
    const int n_base = blockIdx.y * BN;

    float acc[2][8][4];
#pragma unroll
    for (int ma = 0; ma < 2; ma++)
#pragma unroll
        for (int na = 0; na < 8; na++)
#pragma unroll
            for (int i = 0; i < 4; i++) acc[ma][na][i] = 0.f;

    gemm_main(g_A, g_wc + 3 * D_ * D_, m_base, n_base, sA, sB, sA_u, sB_u, acc);

    const int lane = threadIdx.x & 31, warp = threadIdx.x >> 5;
    const int g = lane >> 2, t4 = lane & 3;
    const int wm = warp & 3, wn = warp >> 2;
#pragma unroll
    for (int ma = 0; ma < 2; ma++)
#pragma unroll
        for (int na = 0; na < 8; na++) {
            int m0 = m_base + wm * 32 + ma * 16 + g;
            int n0 = n_base + wn * 64 + na * 8 + 2 * t4;
#pragma unroll
            for (int i = 0; i < 4; i++) {
                int m = m0 + (i >> 1) * 8;
                int n = n0 + (i & 1);
                out[(size_t)m * D_ + n] = acc[ma][na][i];
            }
        }
}

// ---------------------------------------------------------------------------
// Flash attention. CTA = (b,h,128-q-tile), 128 thr / 4 warps, warp = 32 rows
// (two 16-row blocks). Double-buffered cp.async K/V. V transposed in smem
// (PV B-frags = float2). k-relabel: all frags float2, no P shuffle transpose.
// smem: Qs[128][72] + Ks[2][64][72] + Vt[2][64][72] = 110,592 B.
// ---------------------------------------------------------------------------
#define FS 72
#define OFF_K (128 * FS)
#define OFF_V (OFF_K + 2 * 64 * FS)
#define FLASH_SMEM ((OFF_V + 2 * 64 * FS) * sizeof(float))

__global__ __launch_bounds__(128, 2) void flash_mma()
{
    extern __shared__ float fsm[];
    float (*Qs)[FS] = (float(*)[FS])(fsm);
    const uint32_t smem_base = (uint32_t)__cvta_generic_to_shared(fsm);

    const int t = (gridDim.x - 1) - blockIdx.x;   // heavy tiles first
    const int h = blockIdx.y;
    const int b = blockIdx.z;
    const int tid  = threadIdx.x;
    const int lane = tid & 31;
    const int w    = tid >> 5;
    const int g  = lane >> 2;
    const int t4 = lane & 3;

    const float* Qp  = g_Q + ((size_t)(b * H_ + h) * S_ + t * 128) * HD_;
    const float* Kp  = g_K + ((size_t)(b * H_ + h) * S_) * HD_;
    const float* Vtp = g_V + ((size_t)(b * H_ + h)) * HD_ * S_;   // [hd][s]

    // stage Q: 2048 chunks, 128 thr -> 16 iters
#pragma unroll
    for (int it = 0; it < 16; it++) {
        int f = tid + it * 128;
        int r = f >> 4, c = (f & 15) * 4;
        cpa16(smem_base + (uint32_t)(r * FS + c) * 4u, &Qp[(size_t)r * HD_ + c]);
    }
    // stage K0 (rows=j, cols=hd) and Vt0 (rows=hd, cols=j)
#pragma unroll
    for (int it = 0; it < 8; it++) {
        int f = tid + it * 128;
        int r = f >> 4, c = (f & 15) * 4;
        cpa16(smem_base + (uint32_t)(OFF_K + r * FS + c) * 4u, &Kp[(size_t)r * HD_ + c]);
        cpa16(smem_base + (uint32_t)(OFF_V + r * FS + c) * 4u, &Vtp[(size_t)r * S_ + c]);
    }
    cp_commit();

    const float slope2 = exp2f(-0.5f * (float)(h + 1)) * LOG2E;
    int qr[2][2];
#pragma unroll
    for (int rb = 0; rb < 2; rb++) {
        qr[rb][0] = t * 128 + w * 32 + rb * 16 + g;
        qr[rb][1] = qr[rb][0] + 8;
    }

    float o[2][8][4];
    float mr[2][2], lr[2][2];
#pragma unroll
    for (int rb = 0; rb < 2; rb++) {
        mr[rb][0] = mr[rb][1] = -INFINITY;
        lr[rb][0] = lr[rb][1] = 0.f;
#pragma unroll
        for (int da = 0; da < 8; da++)
#pragma unroll
            for (int i = 0; i < 4; i++) o[rb][da][i] = 0.f;
    }

    const int j_end = t * 128 + 64;
    for (int j0 = 0; j0 <= j_end; j0 += 64) {
        const int cur = (j0 >> 6) & 1;
        if (j0 + 64 <= j_end) {
            const int nb = cur ^ 1;
#pragma unroll
            for (int it = 0; it < 8; it++) {
                int f = tid + it * 128;
                int r = f >> 4, c = (f & 15) * 4;
                cpa16(smem_base + (uint32_t)(OFF_K + (nb * 64 + r) * FS + c) * 4u,
                      &Kp[(size_t)(j0 + 64 + r) * HD_ + c]);
                cpa16(smem_base + (uint32_t)(OFF_V + (nb * 64 + r) * FS + c) * 4u,
                      &Vtp[(size_t)r * S_ + j0 + 64 + c]);
            }
            cp_commit();
            cp_wait<1>();
        } else {
            cp_wait<0>();
        }
        __syncthreads();

        const float (*Kc)[FS] = (const float(*)[FS])(fsm + OFF_K) + cur * 64;
        const float (*Vc)[FS] = (const float(*)[FS])(fsm + OFF_V) + cur * 64;

        // S = Q @ K^T  (two 16-row blocks per warp; K frag shared)
        float s[2][8][4];
#pragma unroll
        for (int rb = 0; rb < 2; rb++)
#pragma unroll
            for (int na = 0; na < 8; na++)
#pragma unroll
                for (int i = 0; i < 4; i++) s[rb][na][i] = 0.f;

#pragma unroll
        for (int kk = 0; kk < 8; kk++) {
            uint32_t aq[2][4];
#pragma unroll
            for (int rb = 0; rb < 2; rb++) {
                int row = w * 32 + rb * 16 + g;
                float2 lo = *(const float2*)&Qs[row][kk * 8 + 2 * t4];
                float2 hi = *(const float2*)&Qs[row + 8][kk * 8 + 2 * t4];
                aq[rb][0] = __float_as_uint(lo.x);
                aq[rb][1] = __float_as_uint(hi.x);
                aq[rb][2] = __float_as_uint(lo.y);
                aq[rb][3] = __float_as_uint(hi.y);
            }
#pragma unroll
            for (int na = 0; na < 8; na++) {
                float2 bv = *(const float2*)&Kc[na * 8 + g][kk * 8 + 2 * t4];
                uint32_t bf[2] = { __float_as_uint(bv.x), __float_as_uint(bv.y) };
                mma8(s[0][na], aq[0], bf);
                mma8(s[1][na], aq[1], bf);
            }
        }

        // ALiBi (base-2) + causal, per row-block
#pragma unroll
        for (int rb = 0; rb < 2; rb++) {
            const bool nm = (j0 + 63) > (t * 128 + w * 32 + rb * 16);
#pragma unroll
            for (int na = 0; na < 8; na++) {
                int jc = j0 + na * 8 + 2 * t4;
                s[rb][na][0] += slope2 * (float)(jc - qr[rb][0]);
                s[rb][na][1] += slope2 * (float)(jc + 1 - qr[rb][0]);
                s[rb][na][2] += slope2 * (float)(jc - qr[rb][1]);
                s[rb][na][3] += slope2 * (float)(jc + 1 - qr[rb][1]);
                if (nm) {
                    if (jc     > qr[rb][0]) s[rb][na][0] = -1e30f;
                    if (jc + 1 > qr[rb][0]) s[rb][na][1] = -1e30f;
                    if (jc     > qr[rb][1]) s[rb][na][2] = -1e30f;
                    if (jc + 1 > qr[rb][1]) s[rb][na][3] = -1e30f;
                }
            }
        }

        // online softmax (base-2) per row-block; reduce over t4 lanes
#pragma unroll
        for (int rb = 0; rb < 2; rb++) {
            float mxA = -INFINITY, mxB = -INFINITY;
#pragma unroll
            for (int na = 0; na < 8; na++) {
                mxA = fmaxf(mxA, fmaxf(s[rb][na][0], s[rb][na][1]));
                mxB = fmaxf(mxB, fmaxf(s[rb][na][2], s[rb][na][3]));
            }
            mxA = fmaxf(mxA, __shfl_xor_sync(0xffffffffu, mxA, 1));
            mxA = fmaxf(mxA, __shfl_xor_sync(0xffffffffu, mxA, 2));
            mxB = fmaxf(mxB, __shfl_xor_sync(0xffffffffu, mxB, 1));
            mxB = fmaxf(mxB, __shfl_xor_sync(0xffffffffu, mxB, 2));

            float mnA = fmaxf(mr[rb][0], mxA), mnB = fmaxf(mr[rb][1], mxB);
            float aAl = exp2f(mr[rb][0] - mnA), aBl = exp2f(mr[rb][1] - mnB);
            mr[rb][0] = mnA; mr[rb][1] = mnB;

            float sumA = 0.f, sumB = 0.f;
#pragma unroll
            for (int na = 0; na < 8; na++) {
                s[rb][na][0] = exp2f(s[rb][na][0] - mnA);
                s[rb][na][1] = exp2f(s[rb][na][1] - mnA);
                s[rb][na][2] = exp2f(s[rb][na][2] - mnB);
                s[rb][na][3] = exp2f(s[rb][na][3] - mnB);
                sumA += s[rb][na][0] + s[rb][na][1];
                sumB += s[rb][na][2] + s[rb][na][3];
            }
            sumA += __shfl_xor_sync(0xffffffffu, sumA, 1);
            sumA += __shfl_xor_sync(0xffffffffu, sumA, 2);
            sumB += __shfl_xor_sync(0xffffffffu, sumB, 1);
            sumB += __shfl_xor_sync(0xffffffffu, sumB, 2);
            lr[rb][0] = lr[rb][0] * aAl + sumA;
            lr[rb][1] = lr[rb][1] * aBl + sumB;

#pragma unroll
            for (int da = 0; da < 8; da++) {
                o[rb][da][0] *= aAl; o[rb][da][1] *= aAl;
                o[rb][da][2] *= aBl; o[rb][da][3] *= aBl;
            }
        }

        // O += P @ V. P a-frags directly from s (relabel); V^T b-frags float2.
#pragma unroll
        for (int kk = 0; kk < 8; kk++) {
            uint32_t ap[2][4];
#pragma unroll
            for (int rb = 0; rb < 2; rb++) {
                ap[rb][0] = f2tf(s[rb][kk][0]);
                ap[rb][1] = f2tf(s[rb][kk][2]);
                ap[rb][2] = f2tf(s[rb][kk][1]);
                ap[rb][3] = f2tf(s[rb][kk][3]);
            }
#pragma unroll
            for (int da = 0; da < 8; da++) {
                float2 vv = *(const float2*)&Vc[da * 8 + g][kk * 8 + 2 * t4];
                uint32_t bf[2] = { __float_as_uint(vv.x), __float_as_uint(vv.y) };
                mma8(o[0][da], ap[0], bf);
                mma8(o[1][da], ap[1], bf);
            }
        }
        __syncthreads();
    }

    // normalize + write [B,S,D] (tf32-rounded for out_gemm)
    uint32_t* Aout = (uint32_t*)g_A;
#pragma unroll
    for (int rb = 0; rb < 2; rb++) {
        const float invA = 1.0f / lr[rb][0], invB = 1.0f / lr[rb][1];
#pragma unroll
        for (int da = 0; da < 8; da++) {
            int col = h * 64 + da * 8 + 2 * t4;
            size_t rA = ((size_t)b * S_ + qr[rb][0]) * D_ + col;
            size_t rB = ((size_t)b * S_ + qr[rb][1]) * D_ + col;
            Aout[rA]     = f2tf(o[rb][da][0] * invA);
            Aout[rA + 1] = f2tf(o[rb][da][1] * invA);
            Aout[rB]     = f2tf(o[rb][da][2] * invB);
            Aout[rB + 1] = f2tf(o[rb][da][3] * invB);
        }
    }
}

// ---------------------------------------------------------------------------
extern "C" void kernel_launch(void* const* d_in, const int* in_sizes, int n_in,
                              void* d_out, int out_size)
{
    const float* x  = (const float*)d_in[0];
    // d_in[1] = causal mask, applied analytically
    const float* Wq = (const float*)d_in[2];
    const float* Wk = (const float*)d_in[3];
    const float* Wv = (const float*)d_in[4];
    const float* Wo = (const float*)d_in[5];
    float* out = (float*)d_out;

    cudaFuncSetAttribute(qkv_gemm, cudaFuncAttributeMaxDynamicSharedMemorySize, (int)GEMM_SMEM);
    cudaFuncSetAttribute(out_gemm, cudaFuncAttributeMaxDynamicSharedMemorySize, (int)GEMM_SMEM);
    cudaFuncSetAttribute(flash_mma, cudaFuncAttributeMaxDynamicSharedMemorySize, (int)FLASH_SMEM);

    dim3 g0(1024, 5);
    precvt<<<g0, 256>>>(x, Wq, Wk, Wv, Wo);

    dim3 g1(M_ / BM, 24);                 // 3 weights x 8 n-tiles
    qkv_gemm<<<g1, 256, GEMM_SMEM>>>();

    dim3 g2(S_ / 128, H_, B_);
    flash_mma<<<g2, 128, FLASH_SMEM>>>();

    dim3 g3(M_ / BM, D_ / BN);
    out_gemm<<<g3, 256, GEMM_SMEM>>>(out);
}